// round 6
// baseline (speedup 1.0000x reference)
#include <cuda_runtime.h>
#include <math.h>

// FlexibleLogisticModel: f = sigmoid( sum_f w[f] * alpha[ord(f)] * monomial_f(x) ),
// all multiset monomials deg 0..4 in D=64 vars, lex (CWR) order. Never reads E.
//
// TT[p] = x_{i3} x_{i4} over pairs i3<=i4 (lex, 2080 entries, smem). Then the
// deg2|deg3|deg4 weight regions form ONE contiguous array starting at w[65]:
//   element f needs  w[65+f] * scale(item) * TT[ttbase(item) + k]
// where items are: [deg2: 1 item len 2080] [deg3: 64 items] [deg4: 2080 items],
// each item's TT operand a contiguous TT tail. Warps take equal contiguous
// ELEMENT slices (load-balanced), closed-form-unrank their start item, then
// walk items incrementally. All loads coalesced (lane-consecutive).
// Single fused kernel: last block applies sigmoid + resets accumulators.

#define D 64
#define NPAIR 2080                 // C(65,2)
#define N3 45760                   // C(66,3)
#define N4 766480                  // C(67,4)
#define E_TOT (NPAIR + N3 + N4)    // 814320 elements, w[65..]
#define W_BASE 65
#define TPB 256
#define NBLK 296                   // 2 CTAs/SM on 148 SMs, single wave
#define NWARP (NBLK * (TPB / 32))  // 2368

__device__ double   g_acc   = 0.0;
__device__ unsigned g_count = 0;

__device__ __forceinline__ int C2i(int n) { return (n >= 2) ? (n * (n - 1)) / 2 : 0; }
__device__ __forceinline__ int C3i(int n) { return (n >= 3) ? (n * (n - 1) * (n - 2)) / 6 : 0; }
__device__ __forceinline__ int C4i(int n) { return (n >= 4) ? (n * (n - 1) * (n - 2) * (n - 3)) / 24 : 0; }

// smallest n with Ck(n) >= v (v >= 1), estimate + short fixup
__device__ __forceinline__ int inv_C2(int v) {
    int n = (int)(0.5f * (1.0f + sqrtf(8.0f * (float)v + 1.0f)));
    n = (n > 2) ? n - 1 : 2;
    while (C2i(n) < v) n++;
    return n;
}
__device__ __forceinline__ int inv_C3(int v) {
    int n = (int)cbrtf(6.0f * (float)v);
    n = (n > 4) ? n - 2 : 3;
    while (C3i(n) < v) n++;
    return n;
}
__device__ __forceinline__ int inv_C4(int v) {
    int n = (int)sqrtf(sqrtf(24.0f * (float)v));
    n = (n > 5) ? n - 2 : 4;
    while (C4i(n) < v) n++;
    return n;
}

__global__ void __launch_bounds__(TPB)
poly_fused_kernel(const float* __restrict__ x,
                  const float* __restrict__ w,
                  const float* __restrict__ alphas,
                  float* __restrict__ out)
{
    __shared__ float  xs[D];
    __shared__ float  al[5];
    __shared__ float  TT[NPAIR];
    __shared__ double warp_sums[TPB / 32];

    const int tid  = threadIdx.x;
    const int lane = tid & 31;
    if (tid < D) xs[tid] = x[tid];
    if (tid < 5) al[tid] = alphas[tid];
    __syncthreads();

    // Build TT: entry p=(i3,i4) lex -> xs[i3]*xs[i4]
    for (int p = tid; p < NPAIR; p += TPB) {
        const int rem = NPAIR - p;
        const int n = inv_C2(rem);          // n = 65 - i3
        const int i3 = 65 - n;
        const int i4 = i3 + (C2i(n) - rem);
        TT[p] = xs[i3] * xs[i4];
    }
    __syncthreads();

    const int gw = blockIdx.x * (TPB / 32) + (tid >> 5);
    double local = 0.0;

    // deg-0 and deg-1 terms (w[0..64]) handled by warp 0
    if (gw == 0) {
        float s = al[1] * (w[1 + lane] * xs[lane] + w[33 + lane] * xs[32 + lane]);
        if (lane == 0) s += al[0] * w[0];
        local += (double)s;
    }

    // Equal contiguous element slices
    const int per = (E_TOT + NWARP - 1) / NWARP;   // 344
    int e = gw * per;
    const int eEnd = (e + per < E_TOT) ? e + per : E_TOT;

    if (e < eEnd) {
        // ---- unrank start element e -> (region, i1, i2, k, L) ----
        int region, i1 = 0, i2 = 0, k, L;
        float scale;
        if (e < NPAIR) {
            region = 2; L = NPAIR; k = e; scale = al[2];
        } else if (e < NPAIR + N3) {
            const int e3 = e - NPAIR;
            const int rem = N3 - e3;                 // [1, 45760]
            const int b = inv_C3(rem);               // b = 66 - i1
            i1 = 66 - b;
            k  = C3i(b) - rem;
            L  = C2i(65 - i1);
            scale = al[3] * xs[i1];
            region = 3;
        } else {
            const int e4 = e - NPAIR - N3;
            const int rem = N4 - e4;                 // [1, 766480]
            const int a = inv_C4(rem);               // a = 67 - i1
            i1 = 67 - a;
            const int r1 = C4i(a) - rem;
            const int rem3 = C3i(66 - i1) - r1;      // [1, C3(66-i1)]
            const int b = inv_C3(rem3);              // b = 66 - i2
            i2 = 66 - b;
            k  = C3i(b) - rem3;
            L  = C2i(65 - i2);
            scale = al[4] * xs[i1] * xs[i2];
            region = 4;
        }
        int ttb = NPAIR - L;

        // ---- walk items over our element range ----
        while (e < eEnd) {
            const int rem_item = L - k;
            const int rem_rng  = eEnd - e;
            const int run = (rem_item < rem_rng) ? rem_item : rem_rng;

            const float* __restrict__ wp = w + W_BASE + e;
            const float* tp = TT + ttb + k;

            float s0 = 0.f, s1 = 0.f, s2 = 0.f, s3 = 0.f;
            int j = lane;
            for (; j + 224 < run; j += 256) {        // 8 loads in flight
                const float a0 = wp[j];        const float a1 = wp[j + 32];
                const float a2 = wp[j + 64];   const float a3 = wp[j + 96];
                const float a4 = wp[j + 128];  const float a5 = wp[j + 160];
                const float a6 = wp[j + 192];  const float a7 = wp[j + 224];
                s0 += a0 * tp[j];        s1 += a1 * tp[j + 32];
                s2 += a2 * tp[j + 64];   s3 += a3 * tp[j + 96];
                s0 += a4 * tp[j + 128];  s1 += a5 * tp[j + 160];
                s2 += a6 * tp[j + 192];  s3 += a7 * tp[j + 224];
            }
            for (; j + 96 < run; j += 128) {         // 4 loads in flight
                const float a0 = wp[j];       const float a1 = wp[j + 32];
                const float a2 = wp[j + 64];  const float a3 = wp[j + 96];
                s0 += a0 * tp[j];       s1 += a1 * tp[j + 32];
                s2 += a2 * tp[j + 64];  s3 += a3 * tp[j + 96];
            }
            for (; j < run; j += 32) s0 += wp[j] * tp[j];
            local += (double)(scale * ((s0 + s1) + (s2 + s3)));

            e += run; k += run;
            if (k == L && e < eEnd) {
                // advance to next item (regions are back-to-back in w)
                k = 0;
                if (region == 2) { region = 3; i1 = 0; }
                else if (region == 3) {
                    if (++i1 == D) { region = 4; i1 = 0; i2 = 0; }
                } else {
                    if (++i2 == D) { ++i1; i2 = i1; }
                }
                if (region == 3) { L = C2i(65 - i1); scale = al[3] * xs[i1]; }
                else             { L = C2i(65 - i2); scale = al[4] * xs[i1] * xs[i2]; }
                ttb = NPAIR - L;
            }
        }
    }

    // ---- warp + block reduction (double) ----
    #pragma unroll
    for (int o = 16; o > 0; o >>= 1)
        local += __shfl_down_sync(0xffffffffu, local, o);
    if (lane == 0) warp_sums[tid >> 5] = local;
    __syncthreads();

    if (tid == 0) {
        double bs = 0.0;
        #pragma unroll
        for (int i = 0; i < TPB / 32; i++) bs += warp_sums[i];
        atomicAdd(&g_acc, bs);
        __threadfence();
        const unsigned done = atomicAdd(&g_count, 1u);
        if (done == NBLK - 1) {
            const double a = atomicAdd(&g_acc, 0.0);  // all contributions visible
            out[0] = (float)(1.0 / (1.0 + exp(-a)));
            g_acc = 0.0;     // reset for next graph replay
            g_count = 0u;
        }
    }
}

extern "C" void kernel_launch(void* const* d_in, const int* in_sizes, int n_in,
                              void* d_out, int out_size)
{
    const float* x      = (const float*)d_in[0];
    const float* w      = (const float*)d_in[1];
    const float* alphas = (const float*)d_in[2];
    // d_in[3] = E (constant, NOT read), d_in[4] = ord_ids (NOT read)
    float* out = (float*)d_out;

    poly_fused_kernel<<<NBLK, TPB>>>(x, w, alphas, out);
}

// round 7
// speedup vs baseline: 1.5403x; 1.5403x over previous
#include <cuda_runtime.h>
#include <math.h>

// FlexibleLogisticModel: f = sigmoid( sum_f w[f] * alpha[ord(f)] * monomial_f(x) ),
// all multiset monomials deg 0..4 in D=64 vars, lex (CWR) order. Never reads E.
//
// TT[p] = x_{i3} x_{i4} over pairs i3<=i4 (2080, smem). Work = uniform <=128-elem
// chunks that never span items:
//   groups: g=0 deg-2 (L=2080, 1 item); g=1..57 deg-3 i1=g-1 (1 item, L=C2(65-i1));
//           g=58..114 deg-4 i2=g-58 (i2+1 items, L=C2(65-i2)); all L>=32.
// Each warp takes a contiguous run of ~3 units: 1 binary search + O(1) walks.
// Unit = 4 predicated coalesced LDG + 4 LDS -> exactly 1 L2 round trip.
// Short items (deg-4 i2>=57, deg-3 i1>=57; ~5K elems) run per-thread with
// full-MLP dots. Single fused kernel; last block applies sigmoid + resets.

#define D 64
#define NPAIR 2080
#define N3 45760
#define N4 766480
#define NGROUP 115
#define TPB 256
#define NBLK 296
#define NW (NBLK * (TPB / 32))   // 2368 warps

__device__ double   g_acc   = 0.0;
__device__ unsigned g_count = 0;

__device__ __forceinline__ int C2i(int n) { return (n >= 2) ? (n * (n - 1)) / 2 : 0; }
__device__ __forceinline__ int C3i(int n) { return (n >= 3) ? (n * (n - 1) * (n - 2)) / 6 : 0; }
__device__ __forceinline__ int C4i(int n) { return (n >= 4) ? (n * (n - 1) * (n - 2) * (n - 3)) / 24 : 0; }

__device__ __forceinline__ int inv_C2(int v) {   // smallest n with C2(n) >= v
    int n = (int)(0.5f * (1.0f + sqrtf(8.0f * (float)v + 1.0f)));
    n = (n > 2) ? n - 1 : 2;
    while (C2i(n) < v) n++;
    return n;
}

// deg-4 item (i1,i2) start offset in w
__device__ __forceinline__ int off4(int i1, int i2) {
    return 47905 + (N4 - C4i(67 - i1)) + (C3i(66 - i1) - C3i(66 - i2));
}

__global__ void __launch_bounds__(TPB)
poly_fused_kernel(const float* __restrict__ x,
                  const float* __restrict__ w,
                  const float* __restrict__ alphas,
                  float* __restrict__ out)
{
    __shared__ float  xs[D];
    __shared__ float  al[5];
    __shared__ float  TT[NPAIR];
    __shared__ int    sL[NGROUP];     // item length per group
    __shared__ int    sN[NGROUP];     // items per group
    __shared__ int    sC[NGROUP];     // chunks per item
    __shared__ int    pref[NGROUP + 1];
    __shared__ int    wpart[4];
    __shared__ double warp_sums[TPB / 32];

    const int tid  = threadIdx.x;
    const int lane = tid & 31;
    if (tid < D) xs[tid] = x[tid];
    if (tid < 5) al[tid] = alphas[tid];

    // ---- group table + unit-count prefix scan (threads 0..114, 4 warps) ----
    int ucnt = 0;
    if (tid < NGROUP) {
        int L, n;
        if (tid == 0)      { L = NPAIR; n = 1; }
        else if (tid <= 57){ int i1 = tid - 1;  L = C2i(65 - i1); n = 1; }
        else               { int i2 = tid - 58; L = C2i(65 - i2); n = i2 + 1; }
        sL[tid] = L; sN[tid] = n;
        const int cpi = (L + 127) >> 7;
        sC[tid] = cpi;
        ucnt = n * cpi;
    }
    int v = ucnt;
    #pragma unroll
    for (int o = 1; o < 32; o <<= 1) {
        int nb = __shfl_up_sync(0xffffffffu, v, o);
        if (lane >= o) v += nb;
    }
    if (lane == 31 && tid < 128) wpart[tid >> 5] = v;
    __syncthreads();
    if (tid < NGROUP) {
        int add = 0;
        for (int k = 0; k < (tid >> 5); k++) add += wpart[k];
        v += add;
        pref[tid] = v - ucnt;
        if (tid == NGROUP - 1) pref[NGROUP] = v;
    }
    // ---- build TT while scan settles ----
    __syncthreads();
    for (int p = tid; p < NPAIR; p += TPB) {
        const int rem = NPAIR - p;
        const int n = inv_C2(rem);           // n = 65 - i3
        const int i3 = 65 - n;
        const int i4 = i3 + (C2i(n) - rem);
        TT[p] = xs[i3] * xs[i4];
    }
    __syncthreads();

    const int gw = blockIdx.x * (TPB / 32) + (tid >> 5);
    const int gt = blockIdx.x * TPB + tid;
    double local = 0.0;

    // ---- per-thread short-item tail + deg 0/1 ----
    if (gt < 427) {
        // deg-4, i2 in [57,63], items ordered (i2, i1)
        int t = gt, i2 = 57;
        while (t >= i2 + 1) { t -= (i2 + 1); i2++; }
        const int i1 = t;
        const int L = C2i(65 - i2);          // <= 28
        const float* wp = w + off4(i1, i2);
        const float* tp = TT + (NPAIR - L);
        float s0 = 0.f, s1 = 0.f, s2 = 0.f, s3 = 0.f;
        int k = 0;
        for (; k + 3 < L; k += 4) {
            s0 += wp[k] * tp[k];     s1 += wp[k+1] * tp[k+1];
            s2 += wp[k+2] * tp[k+2]; s3 += wp[k+3] * tp[k+3];
        }
        for (; k < L; k++) s0 += wp[k] * tp[k];
        local += (double)(al[4] * xs[i1] * xs[i2] * ((s0 + s1) + (s2 + s3)));
    } else if (gt < 434) {
        // deg-3, i1 in [57,63]
        const int i1 = 57 + (gt - 427);
        const int L = C2i(65 - i1);          // <= 28
        const float* wp = w + 2145 + (N3 - C3i(66 - i1));
        const float* tp = TT + (NPAIR - L);
        float s0 = 0.f, s1 = 0.f, s2 = 0.f, s3 = 0.f;
        int k = 0;
        for (; k + 3 < L; k += 4) {
            s0 += wp[k] * tp[k];     s1 += wp[k+1] * tp[k+1];
            s2 += wp[k+2] * tp[k+2]; s3 += wp[k+3] * tp[k+3];
        }
        for (; k < L; k++) s0 += wp[k] * tp[k];
        local += (double)(al[3] * xs[i1] * ((s0 + s1) + (s2 + s3)));
    } else if (gt == 434) {
        // deg-0 and deg-1
        float s0 = 0.f, s1 = 0.f, s2 = 0.f, s3 = 0.f;
        #pragma unroll
        for (int k = 0; k < 64; k += 4) {
            s0 += w[1+k] * xs[k];     s1 += w[2+k] * xs[k+1];
            s2 += w[3+k] * xs[k+2];   s3 += w[4+k] * xs[k+3];
        }
        local += (double)(al[0] * w[0])
               + (double)(al[1] * ((s0 + s1) + (s2 + s3)));
    }

    // ---- cooperative uniform units ----
    const int U   = pref[NGROUP];
    const int upw = (U + NW - 1) / NW;
    int u = gw * upw;
    const int uEnd = (u + upw < U) ? u + upw : U;

    if (u < uEnd) {
        // one binary search for the starting group
        int lo = 0, hi = NGROUP - 1;
        #pragma unroll
        for (int it = 0; it < 7; ++it) {
            const int mid = (lo + hi + 1) >> 1;
            if (pref[mid] <= u) lo = mid; else hi = mid - 1;
        }
        int g = lo;
        int L = sL[g], n = sN[g], cpi = sC[g];
        const int uloc = u - pref[g];
        int item = (int)((unsigned)uloc / (unsigned)cpi);
        int c    = uloc - item * cpi;

        while (u < uEnd) {
            // unit (g, item, c)
            int off; float scale;
            if (g == 0)       { off = 65; scale = al[2]; }
            else if (g <= 57) { const int i1 = g - 1;
                                off = 2145 + (N3 - C3i(66 - i1));
                                scale = al[3] * xs[i1]; }
            else              { const int i2 = g - 58; const int i1 = item;
                                off = off4(i1, i2);
                                scale = al[4] * xs[i1] * xs[i2]; }
            const int k0  = c << 7;
            int len = L - k0; if (len > 128) len = 128;
            const float* __restrict__ wp = w + off + k0;
            const float* tp = TT + (NPAIR - L) + k0;

            float s0 = 0.f, s1 = 0.f, s2 = 0.f, s3 = 0.f;
            if (lane      < len) s0 = wp[lane]      * tp[lane];
            if (lane + 32 < len) s1 = wp[lane + 32] * tp[lane + 32];
            if (lane + 64 < len) s2 = wp[lane + 64] * tp[lane + 64];
            if (lane + 96 < len) s3 = wp[lane + 96] * tp[lane + 96];
            local += (double)(scale * ((s0 + s1) + (s2 + s3)));

            // advance to next unit
            ++u;
            if (++c == cpi) {
                c = 0;
                if (++item == n) {
                    item = 0;
                    if (++g < NGROUP) { L = sL[g]; n = sN[g]; cpi = sC[g]; }
                }
            }
        }
    }

    // ---- warp + block reduction (double) ----
    #pragma unroll
    for (int o = 16; o > 0; o >>= 1)
        local += __shfl_down_sync(0xffffffffu, local, o);
    if (lane == 0) warp_sums[tid >> 5] = local;
    __syncthreads();

    if (tid == 0) {
        double bs = 0.0;
        #pragma unroll
        for (int i = 0; i < TPB / 32; i++) bs += warp_sums[i];
        atomicAdd(&g_acc, bs);
        __threadfence();
        const unsigned done = atomicAdd(&g_count, 1u);
        if (done == NBLK - 1) {
            const double a = atomicAdd(&g_acc, 0.0);
            out[0] = (float)(1.0 / (1.0 + exp(-a)));
            g_acc = 0.0;     // reset for next graph replay
            g_count = 0u;
        }
    }
}

extern "C" void kernel_launch(void* const* d_in, const int* in_sizes, int n_in,
                              void* d_out, int out_size)
{
    const float* x      = (const float*)d_in[0];
    const float* w      = (const float*)d_in[1];
    const float* alphas = (const float*)d_in[2];
    // d_in[3] = E (constant, NOT read), d_in[4] = ord_ids (NOT read)
    float* out = (float*)d_out;

    poly_fused_kernel<<<NBLK, TPB>>>(x, w, alphas, out);
}

// round 8
// speedup vs baseline: 1.7819x; 1.1569x over previous
#include <cuda_runtime.h>
#include <math.h>

// FlexibleLogisticModel: f = sigmoid( sum_f w[f]*alpha[ord(f)]*monomial_f(x) ),
// all multiset monomials deg 0..4 in D=64 vars, lex CWR order. Never reads E.
//
// Phase A: materialize g_OP[47840] = [pair products (2080) | triple products
// (45760)] in lex order (closed-form unrank per element, coalesced writes).
// Phase B: whole sum = per-segment scaled coalesced dots of w[65+e] * g_OP[e+delta]:
//   seg0 deg2  [0,2080)      delta 0        scale a2
//   seg1 deg3  [2080,47840)  delta 0        scale a3
//   seg2+t deg4 i1=t (t<=51) delta const(t) scale a4*x[t]
// Per-warp contiguous 344-elem ranges hit <=2 segments (all seg lens >= 1365).
// deg-4 tail (i1>=52, 1365 elems) per-lane closed-form. Software grid barrier
// (296 CTAs = 2/SM, all co-resident). Last block: sigmoid + reset.

#define D 64
#define NPAIR 2080
#define N3 45760
#define N4 766480
#define ETOT 814320            // 2080 + 45760 + 766480
#define ECUT 812955            // start of deg-4 item i1=52 (= ETOT - 1365)
#define NSEG 54                // deg2, deg3, deg4 i1=0..51
#define TPB 256
#define NBLK 296
#define NW (NBLK * (TPB / 32)) // 2368 warps
#define PER 344                // ceil(ECUT / NW)
#define TAILW 43               // warps covering the 1365-elem tail (43*32=1376)

__device__ float    g_OP[47840];
__device__ double   g_acc   = 0.0;
__device__ unsigned g_count = 0;
__device__ unsigned g_sync  = 0;

__device__ __forceinline__ int C2i(int n) { return (n >= 2) ? (n * (n - 1)) / 2 : 0; }
__device__ __forceinline__ int C3i(int n) { return (n >= 3) ? (n * (n - 1) * (n - 2)) / 6 : 0; }
__device__ __forceinline__ int C4i(int n) { return (n >= 4) ? (n * (n - 1) * (n - 2) * (n - 3)) / 24 : 0; }

__device__ __forceinline__ int inv_C2(int v) {   // smallest n with C2(n) >= v
    int n = (int)(0.5f * (1.0f + sqrtf(8.0f * (float)v + 1.0f)));
    n = (n > 3) ? n - 1 : 2;
    while (C2i(n) < v) n++;
    return n;
}
__device__ __forceinline__ int inv_C3(int v) {
    int n = (int)cbrtf(6.0f * (float)v);
    n = (n > 4) ? n - 2 : 3;
    while (C3i(n) < v) n++;
    return n;
}
__device__ __forceinline__ int inv_C4(int v) {
    int n = (int)sqrtf(sqrtf(24.0f * (float)v));
    n = (n > 5) ? n - 2 : 4;
    while (C4i(n) < v) n++;
    return n;
}

__global__ void __launch_bounds__(TPB)
poly_fused_kernel(const float* __restrict__ x,
                  const float* __restrict__ w,
                  const float* __restrict__ alphas,
                  float* __restrict__ out)
{
    __shared__ float  xs[D];
    __shared__ float  al[5];
    __shared__ int    bnd[NSEG + 1];
    __shared__ float  sscale[NSEG];
    __shared__ int    sdelta[NSEG];
    __shared__ double warp_sums[TPB / 32];

    const int tid  = threadIdx.x;
    const int lane = tid & 31;
    if (tid < D) xs[tid] = x[tid];
    if (tid < 5) al[tid] = alphas[tid];
    __syncthreads();

    // ---- segment tables (threads 0..54) ----
    if (tid == 0)      { bnd[0] = 0;     sscale[0] = al[2]; sdelta[0] = 0; }
    else if (tid == 1) { bnd[1] = NPAIR; sscale[1] = al[3]; sdelta[1] = 0; }
    else if (tid < NSEG) {
        const int i1 = tid - 2;
        bnd[tid]    = 47840 + (N4 - C4i(67 - i1));
        sscale[tid] = al[4] * xs[i1];
        sdelta[tid] = C4i(67 - i1) - C3i(66 - i1) - N4;
    } else if (tid == NSEG) {
        bnd[NSEG] = ECUT;
    }

    // ---- Phase A: build g_OP (coalesced; <=1 element per thread) ----
    const int gt = blockIdx.x * TPB + tid;
    if (gt < NPAIR) {
        // pair products
        const int rem = NPAIR - gt;
        const int n = inv_C2(rem);
        const int i3 = 65 - n;
        const int i4 = i3 + (C2i(n) - rem);
        g_OP[gt] = xs[i3] * xs[i4];
    } else if (gt < 47840) {
        // triple products: e3 = gt - 2080
        const int e3  = gt - NPAIR;
        const int rem = N3 - e3;
        const int b   = inv_C3(rem);          // b = 66 - j
        const int j   = 66 - b;
        const int k   = C3i(b) - rem;
        const int remp = C2i(65 - j) - k;     // pair remainder within tail
        const int n   = inv_C2(remp);
        const int i3  = 65 - n;
        const int i4  = i3 + (C2i(n) - remp);
        g_OP[gt] = xs[j] * xs[i3] * xs[i4];
    }

    // ---- grid barrier (all 296 CTAs co-resident at 2/SM) ----
    __threadfence();
    __syncthreads();
    if (tid == 0) {
        atomicAdd(&g_sync, 1u);
        while (*(volatile unsigned*)&g_sync < NBLK) { }
    }
    __syncthreads();
    __threadfence();

    // ---- Phase B ----
    const int gw = blockIdx.x * (TPB / 32) + (tid >> 5);
    double local = 0.0;

    // main ranges: <=2 segments per warp
    {
        const int e0 = gw * PER;
        const int e1 = (e0 + PER < ECUT) ? e0 + PER : ECUT;
        if (e0 < ECUT) {
            int lo = 0, hi = NSEG - 1;
            #pragma unroll
            for (int it = 0; it < 6; ++it) {
                const int mid = (lo + hi + 1) >> 1;
                if (bnd[mid] <= e0) lo = mid; else hi = mid - 1;
            }
            int s = lo;
            int e = e0;
            while (e < e1) {
                const int segEnd = bnd[s + 1];
                const int end = (segEnd < e1) ? segEnd : e1;
                const float sc = sscale[s];
                const int   dl = sdelta[s];
                const float* __restrict__ wp = w + 65;
                float a0 = 0.f, a1 = 0.f, a2 = 0.f, a3 = 0.f;
                int j = e + lane;
                for (; j + 96 < end; j += 128) {
                    const float w0 = wp[j];       const float w1 = wp[j + 32];
                    const float w2 = wp[j + 64];  const float w3 = wp[j + 96];
                    const float o0 = g_OP[j + dl];      const float o1 = g_OP[j + 32 + dl];
                    const float o2 = g_OP[j + 64 + dl]; const float o3 = g_OP[j + 96 + dl];
                    a0 += w0 * o0; a1 += w1 * o1; a2 += w2 * o2; a3 += w3 * o3;
                }
                for (; j < end; j += 32) a0 += wp[j] * g_OP[j + dl];
                local += (double)(sc * ((a0 + a1) + (a2 + a3)));
                e = end; ++s;
            }
        }
    }

    // deg-4 tail (i1 >= 52): per-lane closed-form unrank, warps 0..42
    if (gw < TAILW) {
        const int idx = ECUT + gw * 32 + lane;
        if (idx < ETOT) {
            const int e4  = idx - 47840;
            const int rem = N4 - e4;             // [1, 1365]
            const int a   = inv_C4(rem);         // a = 67 - i1
            const int i1  = 67 - a;
            const int k   = C4i(a) - rem;
            const int op  = NPAIR + (N3 - C3i(66 - i1)) + k;
            local += (double)(al[4] * xs[i1] * w[65 + idx] * g_OP[op]);
        }
    }

    // deg-0 / deg-1 on the last warp (it has no main range: 2367*344 > ECUT)
    if (gw == NW - 1) {
        float s = al[1] * (w[1 + lane] * xs[lane] + w[33 + lane] * xs[32 + lane]);
        if (lane == 0) s += al[0] * w[0];
        local += (double)s;
    }

    // ---- warp + block reduction (double) ----
    #pragma unroll
    for (int o = 16; o > 0; o >>= 1)
        local += __shfl_down_sync(0xffffffffu, local, o);
    if (lane == 0) warp_sums[tid >> 5] = local;
    __syncthreads();

    if (tid == 0) {
        double bs = 0.0;
        #pragma unroll
        for (int i = 0; i < TPB / 32; i++) bs += warp_sums[i];
        atomicAdd(&g_acc, bs);
        __threadfence();
        const unsigned done = atomicAdd(&g_count, 1u);
        if (done == NBLK - 1) {
            const double a = atomicAdd(&g_acc, 0.0);   // all contributions visible
            out[0] = (float)(1.0 / (1.0 + exp(-a)));
            g_acc   = 0.0;   // reset for next graph replay
            g_count = 0u;
            g_sync  = 0u;
        }
    }
}

extern "C" void kernel_launch(void* const* d_in, const int* in_sizes, int n_in,
                              void* d_out, int out_size)
{
    const float* x      = (const float*)d_in[0];
    const float* w      = (const float*)d_in[1];
    const float* alphas = (const float*)d_in[2];
    // d_in[3] = E (constant, NOT read), d_in[4] = ord_ids (NOT read)
    float* out = (float*)d_out;

    poly_fused_kernel<<<NBLK, TPB>>>(x, w, alphas, out);
}